// round 5
// baseline (speedup 1.0000x reference)
#include <cuda_runtime.h>
#include <math.h>

#define TT 16384
#define DD 1024
#define II 2048
#define EE 16
#define APAD 20   // smem row stride in floats (conflict-free for frag loads, 16B aligned)

// ---------------- scratch (device globals; no allocation allowed) ----------------
static __device__ float g_H[(TT + 128) * II];   // intermediate [tokens, I], padded rows
static __device__ int   g_perm[TT];
static __device__ float g_scale[TT];
static __device__ int   g_eid[TT];
static __device__ int   g_cnt[EE];
static __device__ int   g_off[EE + 1];
static __device__ int   g_cur[EE];

// ---------------- helpers ----------------
__device__ __forceinline__ unsigned f2tf(float f) {
    unsigned u;
    asm("cvt.rna.tf32.f32 %0, %1;" : "=r"(u) : "f"(f));
    return u;
}
__device__ __forceinline__ float tfr(float f) { return __uint_as_float(f2tf(f)); }

__device__ __forceinline__ void st4tf(float* dst, float4 v) {
    float4 o;
    o.x = tfr(v.x); o.y = tfr(v.y); o.z = tfr(v.z); o.w = tfr(v.w);
    *(float4*)dst = o;
}

__device__ __forceinline__ void mma8(float* c, const unsigned* a, const unsigned* b) {
    asm volatile(
        "mma.sync.aligned.m16n8k8.row.col.f32.tf32.tf32.f32 "
        "{%0,%1,%2,%3}, {%4,%5,%6,%7}, {%8,%9}, {%0,%1,%2,%3};\n"
        : "+f"(c[0]), "+f"(c[1]), "+f"(c[2]), "+f"(c[3])
        : "r"(a[0]), "r"(a[1]), "r"(a[2]), "r"(a[3]), "r"(b[0]), "r"(b[1]));
}

// ---------------- routing ----------------
__global__ void init_counts() {
    int i = threadIdx.x;
    if (i < EE) { g_cnt[i] = 0; g_cur[i] = 0; }
}

__global__ void router_kernel(const float* __restrict__ x, const float* __restrict__ wr) {
    int warp = threadIdx.x >> 5, lane = threadIdx.x & 31;
    int t = blockIdx.x * 8 + warp;
    if (t >= TT) return;
    float acc[EE];
#pragma unroll
    for (int e = 0; e < EE; e++) acc[e] = 0.f;
    const float* xr = x + (size_t)t * DD;
    for (int k = lane; k < DD; k += 32) {
        float xv = xr[k];
#pragma unroll
        for (int e = 0; e < EE; e++) acc[e] += xv * wr[e * DD + k];
    }
#pragma unroll
    for (int e = 0; e < EE; e++) {
#pragma unroll
        for (int o = 16; o > 0; o >>= 1) acc[e] += __shfl_xor_sync(0xffffffffu, acc[e], o);
    }
    if (lane == 0) {
        float best = acc[0]; int bi = 0;
#pragma unroll
        for (int e = 1; e < EE; e++) { if (acc[e] > best) { best = acc[e]; bi = e; } }
        g_eid[t] = bi;
        g_scale[t] = 1.f / (1.f + expf(-best));
        atomicAdd(&g_cnt[bi], 1);
    }
}

__global__ void offsets_kernel() {
    if (threadIdx.x == 0) {
        int s = 0;
        for (int e = 0; e < EE; e++) { g_off[e] = s; s += g_cnt[e]; }
        g_off[EE] = s;
    }
}

__global__ void scatter_kernel() {
    int t = blockIdx.x * blockDim.x + threadIdx.x;
    if (t >= TT) return;
    int e = g_eid[t];
    int p = atomicAdd(&g_cur[e], 1);
    g_perm[g_off[e] + p] = t;
}

// ---------------- GEMM1: H = silu(s*(A@W1^T)) * (s*(A@W3^T)) ----------------
// Block tile 128(M) x 64(N per matrix) x 16(K). 256 threads, 8 warps as 4x2.
__global__ __launch_bounds__(256, 1) void gemm_swiglu(
    const float* __restrict__ X,
    const float* __restrict__ W1b,
    const float* __restrict__ W3b,
    int routed)
{
    __shared__ __align__(16) float sA[2][128 * APAD];
    __shared__ __align__(16) float sB1[2][64 * APAD];
    __shared__ __align__(16) float sB2[2][64 * APAD];
    __shared__ float sS[128];

    int tid = threadIdx.x;
    int n0 = blockIdx.x * 64;
    int rt = blockIdx.y;

    int row0, rows;
    const float *W1p, *W3p;
    if (!routed) {
        row0 = rt * 128; rows = 128; W1p = W1b; W3p = W3b;
    } else {
        int base = 0, e = 0, cnte = 0;
        for (e = 0; e < EE; e++) {
            cnte = g_cnt[e];
            int te = (cnte + 127) >> 7;
            if (rt < base + te) break;
            base += te;
        }
        if (e >= EE) return;
        int lt = rt - base;
        row0 = g_off[e] + lt * 128;
        rows = cnte - lt * 128; if (rows > 128) rows = 128;
        W1p = W1b + (size_t)e * II * DD;
        W3p = W3b + (size_t)e * II * DD;
    }

    if (tid < 128) {
        if (routed) {
            float s = 0.f;
            if (tid < rows) s = g_scale[g_perm[row0 + tid]];
            sS[tid] = s;
        } else sS[tid] = 1.f;
    }

    // staging assignments: each thread stages 2 A rows + 1 row of each B (4 floats each)
    int rA0 = tid >> 2, kq = tid & 3;
    int rA1 = rA0 + 64;
    const float *pA0, *pA1;
    if (routed) {
        int i0 = (rA0 < rows) ? rA0 : 0;
        int i1 = (rA1 < rows) ? rA1 : 0;
        pA0 = X + (size_t)g_perm[row0 + i0] * DD;
        pA1 = X + (size_t)g_perm[row0 + i1] * DD;
    } else {
        pA0 = X + (size_t)(row0 + rA0) * DD;
        pA1 = X + (size_t)(row0 + rA1) * DD;
    }
    int rB = tid >> 2;
    const float* pB1 = W1p + (size_t)(n0 + rB) * DD;
    const float* pB2 = W3p + (size_t)(n0 + rB) * DD;

    const int KT = DD / 16;

    // prologue stage into buf 0
    float4 fa0 = *(const float4*)(pA0 + kq * 4);
    float4 fa1 = *(const float4*)(pA1 + kq * 4);
    float4 fb1 = *(const float4*)(pB1 + kq * 4);
    float4 fb2 = *(const float4*)(pB2 + kq * 4);
    st4tf(&sA[0][rA0 * APAD + kq * 4], fa0);
    st4tf(&sA[0][rA1 * APAD + kq * 4], fa1);
    st4tf(&sB1[0][rB * APAD + kq * 4], fb1);
    st4tf(&sB2[0][rB * APAD + kq * 4], fb2);
    __syncthreads();

    int lane = tid & 31, warp = tid >> 5;
    int wm = warp >> 1, wn = warp & 1;     // 4 x 2 warp grid: warp tile 32x32 (per matrix)
    int gq = lane >> 2, tq = lane & 3;

    float accG[2][4][4] = {}, accU[2][4][4] = {};

    for (int kt = 0; kt < KT; kt++) {
        int cur = kt & 1;
        if (kt + 1 < KT) {
            int k0 = (kt + 1) * 16 + kq * 4;
            fa0 = *(const float4*)(pA0 + k0);
            fa1 = *(const float4*)(pA1 + k0);
            fb1 = *(const float4*)(pB1 + k0);
            fb2 = *(const float4*)(pB2 + k0);
        }
        const float* A  = sA[cur];
        const float* B1 = sB1[cur];
        const float* B2 = sB2[cur];
#pragma unroll
        for (int kk = 0; kk < 16; kk += 8) {
            unsigned a[2][4];
#pragma unroll
            for (int mi = 0; mi < 2; mi++) {
                int m0 = wm * 32 + mi * 16;
                a[mi][0] = __float_as_uint(A[(m0 + gq)     * APAD + kk + tq]);
                a[mi][1] = __float_as_uint(A[(m0 + gq + 8) * APAD + kk + tq]);
                a[mi][2] = __float_as_uint(A[(m0 + gq)     * APAD + kk + tq + 4]);
                a[mi][3] = __float_as_uint(A[(m0 + gq + 8) * APAD + kk + tq + 4]);
            }
#pragma unroll
            for (int ni = 0; ni < 4; ni++) {
                int nn = wn * 32 + ni * 8 + gq;
                unsigned b1v[2], b2v[2];
                b1v[0] = __float_as_uint(B1[nn * APAD + kk + tq]);
                b1v[1] = __float_as_uint(B1[nn * APAD + kk + tq + 4]);
                b2v[0] = __float_as_uint(B2[nn * APAD + kk + tq]);
                b2v[1] = __float_as_uint(B2[nn * APAD + kk + tq + 4]);
#pragma unroll
                for (int mi = 0; mi < 2; mi++) {
                    mma8(accG[mi][ni], a[mi], b1v);
                    mma8(accU[mi][ni], a[mi], b2v);
                }
            }
        }
        if (kt + 1 < KT) {
            int nb = cur ^ 1;
            st4tf(&sA[nb][rA0 * APAD + kq * 4], fa0);
            st4tf(&sA[nb][rA1 * APAD + kq * 4], fa1);
            st4tf(&sB1[nb][rB * APAD + kq * 4], fb1);
            st4tf(&sB2[nb][rB * APAD + kq * 4], fb2);
        }
        __syncthreads();
    }

    // epilogue: apply router weight, SiLU, write H
#pragma unroll
    for (int mi = 0; mi < 2; mi++) {
#pragma unroll
        for (int half = 0; half < 2; half++) {
            int r = wm * 32 + mi * 16 + gq + half * 8;
            bool valid = (!routed) || (r < rows);
            if (valid) {
                float s = sS[r];
                float* Hrow = g_H + (size_t)(row0 + r) * II + n0;
#pragma unroll
                for (int ni = 0; ni < 4; ni++) {
                    float gg = accG[mi][ni][half * 2 + 0] * s;
                    float uu = accU[mi][ni][half * 2 + 0] * s;
                    float h0 = gg / (1.f + expf(-gg)) * uu;
                    gg = accG[mi][ni][half * 2 + 1] * s;
                    uu = accU[mi][ni][half * 2 + 1] * s;
                    float h1 = gg / (1.f + expf(-gg)) * uu;
                    int col = wn * 32 + ni * 8 + 2 * tq;
                    *(float2*)(Hrow + col) = make_float2(h0, h1);
                }
            }
        }
    }
}

// ---------------- GEMM2: OUT = H @ W2^T (shared: write; routed: scatter-add) ----------------
// Block tile 128 x 128 x 16. 256 threads, 8 warps as 2x4 (warp tile 64x32).
__global__ __launch_bounds__(256, 1) void gemm_down(
    const float* __restrict__ Bb,
    float* __restrict__ OUT,
    int routed)
{
    __shared__ __align__(16) float sA[2][128 * APAD];
    __shared__ __align__(16) float sB[2][128 * APAD];

    int tid = threadIdx.x;
    int n0 = blockIdx.x * 128;
    int rt = blockIdx.y;

    int row0, rows;
    const float* Bp;
    if (!routed) {
        row0 = rt * 128; rows = 128; Bp = Bb;
    } else {
        int base = 0, e = 0, cnte = 0;
        for (e = 0; e < EE; e++) {
            cnte = g_cnt[e];
            int te = (cnte + 127) >> 7;
            if (rt < base + te) break;
            base += te;
        }
        if (e >= EE) return;
        int lt = rt - base;
        row0 = g_off[e] + lt * 128;
        rows = cnte - lt * 128; if (rows > 128) rows = 128;
        Bp = Bb + (size_t)e * DD * II;
    }

    int rA0 = tid >> 2, kq = tid & 3;
    int rA1 = rA0 + 64;
    const float* pA0 = g_H + (size_t)(row0 + rA0) * II;  // H padded: safe reads past count
    const float* pA1 = g_H + (size_t)(row0 + rA1) * II;
    const float* pB0 = Bp + (size_t)(n0 + rA0) * II;
    const float* pB1 = Bp + (size_t)(n0 + rA1) * II;

    const int KT = II / 16;

    float4 fa0 = *(const float4*)(pA0 + kq * 4);
    float4 fa1 = *(const float4*)(pA1 + kq * 4);
    float4 fb0 = *(const float4*)(pB0 + kq * 4);
    float4 fb1 = *(const float4*)(pB1 + kq * 4);
    st4tf(&sA[0][rA0 * APAD + kq * 4], fa0);
    st4tf(&sA[0][rA1 * APAD + kq * 4], fa1);
    st4tf(&sB[0][rA0 * APAD + kq * 4], fb0);
    st4tf(&sB[0][rA1 * APAD + kq * 4], fb1);
    __syncthreads();

    int lane = tid & 31, warp = tid >> 5;
    int wm = warp >> 2, wn = warp & 3;     // 2 x 4 warp grid: warp tile 64x32
    int gq = lane >> 2, tq = lane & 3;

    float acc[4][4][4] = {};

    for (int kt = 0; kt < KT; kt++) {
        int cur = kt & 1;
        if (kt + 1 < KT) {
            int k0 = (kt + 1) * 16 + kq * 4;
            fa0 = *(const float4*)(pA0 + k0);
            fa1 = *(const float4*)(pA1 + k0);
            fb0 = *(const float4*)(pB0 + k0);
            fb1 = *(const float4*)(pB1 + k0);
        }
        const float* A = sA[cur];
        const float* B = sB[cur];
#pragma unroll
        for (int kk = 0; kk < 16; kk += 8) {
            unsigned a[4][4];
#pragma unroll
            for (int mi = 0; mi < 4; mi++) {
                int m0 = wm * 64 + mi * 16;
                a[mi][0] = __float_as_uint(A[(m0 + gq)     * APAD + kk + tq]);
                a[mi][1] = __float_as_uint(A[(m0 + gq + 8) * APAD + kk + tq]);
                a[mi][2] = __float_as_uint(A[(m0 + gq)     * APAD + kk + tq + 4]);
                a[mi][3] = __float_as_uint(A[(m0 + gq + 8) * APAD + kk + tq + 4]);
            }
#pragma unroll
            for (int ni = 0; ni < 4; ni++) {
                int nn = wn * 32 + ni * 8 + gq;
                unsigned bv[2];
                bv[0] = __float_as_uint(B[nn * APAD + kk + tq]);
                bv[1] = __float_as_uint(B[nn * APAD + kk + tq + 4]);
#pragma unroll
                for (int mi = 0; mi < 4; mi++) {
                    mma8(acc[mi][ni], a[mi], bv);
                }
            }
        }
        if (kt + 1 < KT) {
            int nb = cur ^ 1;
            st4tf(&sA[nb][rA0 * APAD + kq * 4], fa0);
            st4tf(&sA[nb][rA1 * APAD + kq * 4], fa1);
            st4tf(&sB[nb][rA0 * APAD + kq * 4], fb0);
            st4tf(&sB[nb][rA1 * APAD + kq * 4], fb1);
        }
        __syncthreads();
    }

#pragma unroll
    for (int mi = 0; mi < 4; mi++) {
#pragma unroll
        for (int half = 0; half < 2; half++) {
            int r = wm * 64 + mi * 16 + gq + half * 8;
            if (routed) {
                if (r < rows) {
                    int tok = g_perm[row0 + r];
                    float* Orow = OUT + (size_t)tok * DD;
#pragma unroll
                    for (int ni = 0; ni < 4; ni++) {
                        int col = n0 + wn * 32 + ni * 8 + 2 * tq;
                        float2* p = (float2*)(Orow + col);
                        float2 v = *p;
                        v.x += acc[mi][ni][half * 2 + 0];
                        v.y += acc[mi][ni][half * 2 + 1];
                        *p = v;
                    }
                }
            } else {
                float* Orow = OUT + (size_t)(row0 + r) * DD;
#pragma unroll
                for (int ni = 0; ni < 4; ni++) {
                    int col = n0 + wn * 32 + ni * 8 + 2 * tq;
                    *(float2*)(Orow + col) =
                        make_float2(acc[mi][ni][half * 2 + 0], acc[mi][ni][half * 2 + 1]);
                }
            }
        }
    }
}

// ---------------- launch ----------------
extern "C" void kernel_launch(void* const* d_in, const int* in_sizes, int n_in,
                              void* d_out, int out_size) {
    (void)in_sizes; (void)n_in; (void)out_size;
    const float* x   = (const float*)d_in[0];
    const float* wr  = (const float*)d_in[1];
    const float* w1  = (const float*)d_in[2];
    const float* w3  = (const float*)d_in[3];
    const float* w2  = (const float*)d_in[4];
    const float* wsg = (const float*)d_in[5];
    const float* wsu = (const float*)d_in[6];
    const float* wsd = (const float*)d_in[7];
    float* out = (float*)d_out;

    init_counts<<<1, 32>>>();
    router_kernel<<<TT / 8, 256>>>(x, wr);
    offsets_kernel<<<1, 1>>>();
    scatter_kernel<<<TT / 256, 256>>>();

    // shared expert: H = swiglu(x), out = H @ wsd^T
    gemm_swiglu<<<dim3(II / 64, TT / 128), 256>>>(x, wsg, wsu, 0);
    gemm_down<<<dim3(DD / 128, TT / 128), 256>>>(wsd, out, 0);

    // routed experts (top-1): gathered rows, weight applied pre-activation in epilogue
    gemm_swiglu<<<dim3(II / 64, TT / 128 + EE - 1), 256>>>(x, w1, w3, 1);
    gemm_down<<<dim3(DD / 128, TT / 128 + EE - 1), 256>>>(w2, out, 1);
}

// round 9
// speedup vs baseline: 2.6626x; 2.6626x over previous
#include <cuda_runtime.h>
#include <math.h>
#include <stdint.h>

#define TT 16384
#define DD 1024
#define II 2048
#define EE 16

// tcgen05 only exists in the arch-specific ('a') feature set. The harness also
// compiles a plain compute_103 PTX fallback pass; stub the tcgen05 bodies there
// (that PTX is never executed — the sm_103a cubin is an exact match for the GPU).
#if defined(__CUDA_ARCH__) && !defined(__CUDA_ARCH_FEAT_SM103_ALL)
#define TC_ON 0
#else
#define TC_ON 1
#endif

// ---------------- scratch (device globals; no allocation allowed) ----------------
static __device__ float g_H[(size_t)(TT + 128) * II];   // intermediate [tokens, I], padded rows
static __device__ int   g_perm[TT];
static __device__ float g_scale[TT];
static __device__ int   g_eid[TT];
static __device__ int   g_cnt[EE];
static __device__ int   g_off[EE + 1];
static __device__ int   g_cur[EE];

// ---------------- small helpers ----------------
__device__ __forceinline__ unsigned f2tf(float f) {
    unsigned u;
    asm("cvt.rna.tf32.f32 %0, %1;" : "=r"(u) : "f"(f));
    return u;
}
__device__ __forceinline__ float tfr(float f) { return __uint_as_float(f2tf(f)); }
__device__ __forceinline__ void st4tf(float* dst, float4 v) {
    float4 o;
    o.x = tfr(v.x); o.y = tfr(v.y); o.z = tfr(v.z); o.w = tfr(v.w);
    *(float4*)dst = o;
}

__device__ __forceinline__ uint32_t smem_u32(const void* p) {
    uint32_t a;
    asm("{ .reg .u64 t; cvta.to.shared.u64 t, %1; cvt.u32.u64 %0, t; }" : "=r"(a) : "l"(p));
    return a;
}
__device__ __forceinline__ uint32_t elect1() {
    uint32_t r;
    asm volatile("{ .reg .pred p; elect.sync _|p, 0xFFFFFFFF; selp.b32 %0,1,0,p; }" : "=r"(r));
    return r;
}

#define SWZ128(o) ((o) ^ (((o) >> 3) & 0x70))

__device__ __forceinline__ uint64_t mkdesc(uint32_t addr) {
    // SW128, version=1 (Blackwell), SBO=64, LBO=1, K-major
    return ((uint64_t)2 << 61) | ((uint64_t)1 << 46) | ((uint64_t)64 << 32) |
           ((uint64_t)1 << 16) | ((uint64_t)(addr >> 4) & 0x3FFF);
}

// ---------------- mbarrier (baseline sm_90+: OK in both passes) ----------------
__device__ __forceinline__ void mbar_init(uint32_t a, uint32_t n) {
    asm volatile("mbarrier.init.shared.b64 [%0], %1;" :: "r"(a), "r"(n) : "memory");
}
__device__ __forceinline__ void mbar_wait(uint32_t a, uint32_t ph) {
    uint32_t done;
    asm volatile(
        "{\n .reg .pred p;\n"
        " mbarrier.try_wait.parity.acquire.cta.shared::cta.b64 p, [%1], %2;\n"
        " selp.b32 %0,1,0,p;\n}"
        : "=r"(done) : "r"(a), "r"(ph) : "memory");
    if (!done) {
        asm volatile(
            "{\n .reg .pred P;\n"
            "WL_%=:\n"
            " mbarrier.try_wait.parity.acquire.cta.shared::cta.b64 P, [%0], %1, 0x989680;\n"
            " @P bra WD_%=;\n"
            " bra WL_%=;\n"
            "WD_%=:\n}"
            :: "r"(a), "r"(ph) : "memory");
    }
}

// ---------------- tcgen05 (guarded: real on sm_103a pass, stub on compute_103) ---
__device__ __forceinline__ void tc_alloc(uint32_t smaddr, uint32_t n) {
#if TC_ON
    asm volatile("tcgen05.alloc.cta_group::1.sync.aligned.shared::cta.b32 [%0], %1;"
                 :: "r"(smaddr), "r"(n) : "memory");
#else
    (void)smaddr; (void)n;
#endif
}
__device__ __forceinline__ void tc_relinq() {
#if TC_ON
    asm volatile("tcgen05.relinquish_alloc_permit.cta_group::1.sync.aligned;");
#endif
}
__device__ __forceinline__ void tc_dealloc(uint32_t t, uint32_t n) {
#if TC_ON
    asm volatile("tcgen05.dealloc.cta_group::1.sync.aligned.b32 %0, %1;" :: "r"(t), "r"(n));
#else
    (void)t; (void)n;
#endif
}
__device__ __forceinline__ void tc_commit(uint32_t mbar) {
#if TC_ON
    asm volatile("tcgen05.commit.cta_group::1.mbarrier::arrive::one.shared::cluster.b64 [%0];"
                 :: "r"(mbar) : "memory");
#else
    (void)mbar;
#endif
}
__device__ __forceinline__ void fence_async() {
    asm volatile("fence.proxy.async.shared::cta;" ::: "memory");
}
__device__ __forceinline__ void tc_fence_after() {
#if TC_ON
    asm volatile("tcgen05.fence::after_thread_sync;" ::: "memory");
#endif
}
__device__ __forceinline__ void tc_wait_ld() {
#if TC_ON
    asm volatile("tcgen05.wait::ld.sync.aligned;" ::: "memory");
#endif
}

__device__ __forceinline__ void mma_tf32(uint32_t d, uint64_t a, uint64_t b,
                                         uint32_t idesc, uint32_t en) {
#if TC_ON
    asm volatile(
        "{\n .reg .pred p;\n"
        " setp.ne.u32 p, %5, 0;\n"
        " tcgen05.mma.cta_group::1.kind::tf32 [%0], %1, %2, %3, {%4,%4,%4,%4}, p;\n}"
        :: "r"(d), "l"(a), "l"(b), "r"(idesc), "r"(0u), "r"(en) : "memory");
#else
    (void)d; (void)a; (void)b; (void)idesc; (void)en;
#endif
}

__device__ __forceinline__ void tc_ld32(uint32_t* r, uint32_t addr) {
#if TC_ON
    asm volatile(
        "tcgen05.ld.sync.aligned.32x32b.x32.b32 "
        "{%0, %1, %2, %3, %4, %5, %6, %7, "
        " %8, %9, %10, %11, %12, %13, %14, %15, "
        " %16, %17, %18, %19, %20, %21, %22, %23, "
        " %24, %25, %26, %27, %28, %29, %30, %31}, [%32];"
        : "=r"(r[0]),  "=r"(r[1]),  "=r"(r[2]),  "=r"(r[3]),
          "=r"(r[4]),  "=r"(r[5]),  "=r"(r[6]),  "=r"(r[7]),
          "=r"(r[8]),  "=r"(r[9]),  "=r"(r[10]), "=r"(r[11]),
          "=r"(r[12]), "=r"(r[13]), "=r"(r[14]), "=r"(r[15]),
          "=r"(r[16]), "=r"(r[17]), "=r"(r[18]), "=r"(r[19]),
          "=r"(r[20]), "=r"(r[21]), "=r"(r[22]), "=r"(r[23]),
          "=r"(r[24]), "=r"(r[25]), "=r"(r[26]), "=r"(r[27]),
          "=r"(r[28]), "=r"(r[29]), "=r"(r[30]), "=r"(r[31])
        : "r"(addr));
#else
#pragma unroll
    for (int i = 0; i < 32; i++) r[i] = 0u;
    (void)addr;
#endif
}

// idesc: dtype=F32(1)@4, atype=TF32(2)@7, btype=TF32(2)@10, N/8@17, M/16@24
#define IDESC_TF32 ((1u << 4) | (2u << 7) | (2u << 10) | ((256u / 8) << 17) | ((128u / 16) << 24))

// smem layout (bytes, after 1024-align): A0@0, A1@16384, B0@32768, B1@65536, AUX@98304
#define SM_AB   16384
#define SM_BB   32768
#define SM_B0   32768
#define SM_AUX  98304
#define SM_DYN  (98304 + 1024 + 1024)

// ---------------- routing ----------------
__global__ void init_counts() {
    int i = threadIdx.x;
    if (i < EE) { g_cnt[i] = 0; g_cur[i] = 0; }
}

__global__ void router_kernel(const float* __restrict__ x, const float* __restrict__ wr) {
    int warp = threadIdx.x >> 5, lane = threadIdx.x & 31;
    int t = blockIdx.x * 8 + warp;
    if (t >= TT) return;
    float acc[EE];
#pragma unroll
    for (int e = 0; e < EE; e++) acc[e] = 0.f;
    const float* xr = x + (size_t)t * DD;
    for (int k = lane; k < DD; k += 32) {
        float xv = xr[k];
#pragma unroll
        for (int e = 0; e < EE; e++) acc[e] += xv * wr[e * DD + k];
    }
#pragma unroll
    for (int e = 0; e < EE; e++) {
#pragma unroll
        for (int o = 16; o > 0; o >>= 1) acc[e] += __shfl_xor_sync(0xffffffffu, acc[e], o);
    }
    if (lane == 0) {
        float best = acc[0]; int bi = 0;
#pragma unroll
        for (int e = 1; e < EE; e++) { if (acc[e] > best) { best = acc[e]; bi = e; } }
        g_eid[t] = bi;
        g_scale[t] = 1.f / (1.f + expf(-best));
        atomicAdd(&g_cnt[bi], 1);
    }
}

__global__ void offsets_kernel() {
    if (threadIdx.x == 0) {
        int s = 0;
        for (int e = 0; e < EE; e++) { g_off[e] = s; s += g_cnt[e]; }
        g_off[EE] = s;
    }
}

__global__ void scatter_kernel() {
    int t = blockIdx.x * blockDim.x + threadIdx.x;
    if (t >= TT) return;
    int e = g_eid[t];
    int p = atomicAdd(&g_cur[e], 1);
    g_perm[g_off[e] + p] = t;
}

// ---------------- GEMM1 (tcgen05): H[:,n0b:n0b+128] = silu(s*xW1^T)*(s*xW3^T) ----------------
// M=128 tokens, N=256 (gate rows 0..127 = W1, up rows 128..255 = W3), K=1024 in 32-float chunks.
__global__ void __launch_bounds__(256) gemm1_tc(
    const float* __restrict__ X,
    const float* __restrict__ W1b,
    const float* __restrict__ W3b,
    int routed)
{
    extern __shared__ char smraw[];
    int tid = threadIdx.x, wid = tid >> 5;

    int row0, rows;
    const float *W1p, *W3p;
    if (!routed) {
        row0 = blockIdx.y * 128; rows = 128; W1p = W1b; W3p = W3b;
    } else {
        int base = 0, e = 0, cnte = 0;
        for (e = 0; e < EE; e++) {
            cnte = g_cnt[e];
            int te = (cnte + 127) >> 7;
            if ((int)blockIdx.y < base + te) break;
            base += te;
        }
        if (e >= EE) return;
        int lt = blockIdx.y - base;
        row0 = g_off[e] + lt * 128;
        rows = cnte - lt * 128; if (rows > 128) rows = 128;
        W1p = W1b + (size_t)e * II * DD;
        W3p = W3b + (size_t)e * II * DD;
    }

    uint32_t smr = smem_u32(smraw);
    uint32_t smb = (smr + 1023u) & ~1023u;
    char* sb = smraw + (smb - smr);
    uint32_t aux = smb + SM_AUX;
    float* sS = (float*)(sb + SM_AUX + 32);

    if (wid == 0) { tc_alloc(aux, 256); tc_relinq(); }
    if (tid == 0) { mbar_init(aux + 8, 1); mbar_init(aux + 16, 1); }
    if (tid < 128) {
        float s = 1.f;
        if (routed) s = (tid < rows) ? g_scale[g_perm[row0 + tid]] : 0.f;
        sS[tid] = s;
    }

    int n0b = blockIdx.x * 128;

    const float* pA[4]; uint32_t offA[4];
#pragma unroll
    for (int i = 0; i < 4; i++) {
        int idx = tid + i * 256, r = idx >> 3, kq = idx & 7;
        int gr;
        if (routed) { int rr = (r < rows) ? r : 0; gr = g_perm[row0 + rr]; }
        else gr = row0 + r;
        pA[i] = X + (size_t)gr * DD + kq * 4;
        offA[i] = SWZ128((uint32_t)(r * 128 + kq * 16));
    }
    const float* pB[8]; uint32_t offB[8];
#pragma unroll
    for (int i = 0; i < 8; i++) {
        int idx = tid + i * 256, r = idx >> 3, kq = idx & 7;
        const float* w = (r < 128) ? (W1p + (size_t)(n0b + r) * DD)
                                   : (W3p + (size_t)(n0b + r - 128) * DD);
        pB[i] = w + kq * 4;
        offB[i] = SWZ128((uint32_t)(r * 128 + kq * 16));
    }
    __syncthreads();

    uint32_t tbase;
    asm volatile("ld.shared.b32 %0, [%1];" : "=r"(tbase) : "r"(aux));

    float4 va[4], vb[8];
#pragma unroll
    for (int i = 0; i < 4; i++) va[i] = *(const float4*)(pA[i]);
#pragma unroll
    for (int i = 0; i < 8; i++) vb[i] = *(const float4*)(pB[i]);

    int ph0 = 0, ph1 = 0;
    const int NC = DD / 32;
    for (int c = 0; c < NC; c++) {
        int b = c & 1;
        if (c >= 2) {
            if (b) { mbar_wait(aux + 16, ph1); ph1 ^= 1; }
            else   { mbar_wait(aux + 8,  ph0); ph0 ^= 1; }
        }
        char* abuf = sb + b * SM_AB;
        char* bbuf = sb + SM_B0 + b * SM_BB;
#pragma unroll
        for (int i = 0; i < 4; i++) st4tf((float*)(abuf + offA[i]), va[i]);
#pragma unroll
        for (int i = 0; i < 8; i++) st4tf((float*)(bbuf + offB[i]), vb[i]);
        __syncthreads();
        if (wid == 0) {
            fence_async();
            if (elect1()) {
                uint64_t ad = mkdesc(smb + b * SM_AB);
                uint64_t bd = mkdesc(smb + SM_B0 + b * SM_BB);
#pragma unroll
                for (int ks = 0; ks < 4; ks++)
                    mma_tf32(tbase, ad + ks * 2, bd + ks * 2, IDESC_TF32,
                             (c > 0 || ks > 0) ? 1u : 0u);
                tc_commit(aux + 8 + b * 8);
            }
        }
        if (c + 1 < NC) {
            int co = (c + 1) * 32;
#pragma unroll
            for (int i = 0; i < 4; i++) va[i] = *(const float4*)(pA[i] + co);
#pragma unroll
            for (int i = 0; i < 8; i++) vb[i] = *(const float4*)(pB[i] + co);
        }
    }
    mbar_wait(aux + 16, ph1);   // last chunk (NC-1 odd) committed on buf1
    tc_fence_after();

    if (tid < 128) {
        int r = tid;
        bool ok = (!routed) || (r < rows);
        float s = sS[r];
        float* Hrow = g_H + (size_t)(row0 + r) * II + n0b;
#pragma unroll
        for (int p = 0; p < 4; p++) {
            uint32_t gr[32], ur[32];
            tc_ld32(gr, tbase + p * 32);
            tc_ld32(ur, tbase + 128 + p * 32);
            tc_wait_ld();
            if (ok) {
#pragma unroll
                for (int j = 0; j < 32; j += 4) {
                    float4 h;
                    float gg, uu;
                    gg = __uint_as_float(gr[j + 0]) * s; uu = __uint_as_float(ur[j + 0]) * s;
                    h.x = gg / (1.f + expf(-gg)) * uu;
                    gg = __uint_as_float(gr[j + 1]) * s; uu = __uint_as_float(ur[j + 1]) * s;
                    h.y = gg / (1.f + expf(-gg)) * uu;
                    gg = __uint_as_float(gr[j + 2]) * s; uu = __uint_as_float(ur[j + 2]) * s;
                    h.z = gg / (1.f + expf(-gg)) * uu;
                    gg = __uint_as_float(gr[j + 3]) * s; uu = __uint_as_float(ur[j + 3]) * s;
                    h.w = gg / (1.f + expf(-gg)) * uu;
                    *(float4*)(Hrow + p * 32 + j) = h;
                }
            }
        }
    }
    __syncthreads();
    if (wid == 0) tc_dealloc(tbase, 256);
}

// ---------------- GEMM2 (tcgen05): OUT[:, n0:n0+256] (+)= H @ W2^T ----------------
// M=128, N=256 output cols, K=2048 in 32-float chunks.
__global__ void __launch_bounds__(256) gemm2_tc(
    const float* __restrict__ Bb,
    float* __restrict__ OUT,
    int routed)
{
    extern __shared__ char smraw[];
    int tid = threadIdx.x, wid = tid >> 5;

    int row0, rows;
    const float* Bp;
    if (!routed) {
        row0 = blockIdx.y * 128; rows = 128; Bp = Bb;
    } else {
        int base = 0, e = 0, cnte = 0;
        for (e = 0; e < EE; e++) {
            cnte = g_cnt[e];
            int te = (cnte + 127) >> 7;
            if ((int)blockIdx.y < base + te) break;
            base += te;
        }
        if (e >= EE) return;
        int lt = blockIdx.y - base;
        row0 = g_off[e] + lt * 128;
        rows = cnte - lt * 128; if (rows > 128) rows = 128;
        Bp = Bb + (size_t)e * DD * II;
    }

    uint32_t smr = smem_u32(smraw);
    uint32_t smb = (smr + 1023u) & ~1023u;
    char* sb = smraw + (smb - smr);
    uint32_t aux = smb + SM_AUX;

    if (wid == 0) { tc_alloc(aux, 256); tc_relinq(); }
    if (tid == 0) { mbar_init(aux + 8, 1); mbar_init(aux + 16, 1); }

    int n0 = blockIdx.x * 256;

    const float* pA[4]; uint32_t offA[4];
#pragma unroll
    for (int i = 0; i < 4; i++) {
        int idx = tid + i * 256, r = idx >> 3, kq = idx & 7;
        pA[i] = g_H + (size_t)(row0 + r) * II + kq * 4;   // padded: safe past rows
        offA[i] = SWZ128((uint32_t)(r * 128 + kq * 16));
    }
    const float* pB[8]; uint32_t offB[8];
#pragma unroll
    for (int i = 0; i < 8; i++) {
        int idx = tid + i * 256, r = idx >> 3, kq = idx & 7;
        pB[i] = Bp + (size_t)(n0 + r) * II + kq * 4;
        offB[i] = SWZ128((uint32_t)(r * 128 + kq * 16));
    }
    __syncthreads();

    uint32_t tbase;
    asm volatile("ld.shared.b32 %0, [%1];" : "=r"(tbase) : "r"(aux));

    float4 va[4], vb[8];
#pragma unroll
    for (int i = 0; i < 4; i++) va[i] = *(const float4*)(pA[i]);
#pragma unroll
    for (int i = 0; i < 8; i++) vb[i] = *(const float4*)(pB[i]);

    int ph0 = 0, ph1 = 0;
    const int NC = II / 32;
    for (int c = 0; c < NC; c++) {
        int b = c & 1;
        if (c >= 2) {
            if (b) { mbar_wait(aux + 16, ph1); ph1 ^= 1; }
            else   { mbar_wait(aux + 8,  ph0); ph0 ^= 1; }
        }
        char* abuf = sb + b * SM_AB;
        char* bbuf = sb + SM_B0 + b * SM_BB;
#pragma unroll
        for (int i = 0; i < 4; i++) st4tf((float*)(abuf + offA[i]), va[i]);
#pragma unroll
        for (int i = 0; i < 8; i++) st4tf((float*)(bbuf + offB[i]), vb[i]);
        __syncthreads();
        if (wid == 0) {
            fence_async();
            if (elect1()) {
                uint64_t ad = mkdesc(smb + b * SM_AB);
                uint64_t bd = mkdesc(smb + SM_B0 + b * SM_BB);
#pragma unroll
                for (int ks = 0; ks < 4; ks++)
                    mma_tf32(tbase, ad + ks * 2, bd + ks * 2, IDESC_TF32,
                             (c > 0 || ks > 0) ? 1u : 0u);
                tc_commit(aux + 8 + b * 8);
            }
        }
        if (c + 1 < NC) {
            int co = (c + 1) * 32;
#pragma unroll
            for (int i = 0; i < 4; i++) va[i] = *(const float4*)(pA[i] + co);
#pragma unroll
            for (int i = 0; i < 8; i++) vb[i] = *(const float4*)(pB[i] + co);
        }
    }
    mbar_wait(aux + 16, ph1);   // NC even -> last chunk on buf1
    tc_fence_after();

    if (tid < 128) {
        int r = tid;
        bool ok = (!routed) || (r < rows);
        int tok = 0;
        if (routed && ok) tok = g_perm[row0 + r];
#pragma unroll
        for (int p = 0; p < 8; p++) {
            uint32_t cr[32];
            tc_ld32(cr, tbase + p * 32);
            tc_wait_ld();
            if (ok) {
                if (routed) {
                    float* Orow = OUT + (size_t)tok * DD + n0 + p * 32;
#pragma unroll
                    for (int j = 0; j < 32; j += 4) {
                        float4 v = *(float4*)(Orow + j);
                        v.x += __uint_as_float(cr[j + 0]);
                        v.y += __uint_as_float(cr[j + 1]);
                        v.z += __uint_as_float(cr[j + 2]);
                        v.w += __uint_as_float(cr[j + 3]);
                        *(float4*)(Orow + j) = v;
                    }
                } else {
                    float* Orow = OUT + (size_t)(row0 + r) * DD + n0 + p * 32;
#pragma unroll
                    for (int j = 0; j < 32; j += 4) {
                        float4 v;
                        v.x = __uint_as_float(cr[j + 0]);
                        v.y = __uint_as_float(cr[j + 1]);
                        v.z = __uint_as_float(cr[j + 2]);
                        v.w = __uint_as_float(cr[j + 3]);
                        *(float4*)(Orow + j) = v;
                    }
                }
            }
        }
    }
    __syncthreads();
    if (wid == 0) tc_dealloc(tbase, 256);
}

// ---------------- launch ----------------
extern "C" void kernel_launch(void* const* d_in, const int* in_sizes, int n_in,
                              void* d_out, int out_size) {
    (void)in_sizes; (void)n_in; (void)out_size;
    const float* x   = (const float*)d_in[0];
    const float* wr  = (const float*)d_in[1];
    const float* w1  = (const float*)d_in[2];
    const float* w3  = (const float*)d_in[3];
    const float* w2  = (const float*)d_in[4];
    const float* wsg = (const float*)d_in[5];
    const float* wsu = (const float*)d_in[6];
    const float* wsd = (const float*)d_in[7];
    float* out = (float*)d_out;

    cudaFuncSetAttribute(gemm1_tc, cudaFuncAttributeMaxDynamicSharedMemorySize, SM_DYN);
    cudaFuncSetAttribute(gemm2_tc, cudaFuncAttributeMaxDynamicSharedMemorySize, SM_DYN);

    init_counts<<<1, 32>>>();
    router_kernel<<<TT / 8, 256>>>(x, wr);
    offsets_kernel<<<1, 1>>>();
    scatter_kernel<<<TT / 256, 256>>>();

    // shared expert
    gemm1_tc<<<dim3(II / 128, TT / 128), 256, SM_DYN>>>(x, wsg, wsu, 0);
    gemm2_tc<<<dim3(DD / 256, TT / 128), 256, SM_DYN>>>(wsd, out, 0);

    // routed experts (top-1)
    gemm1_tc<<<dim3(II / 128, TT / 128 + EE - 1), 256, SM_DYN>>>(x, w1, w3, 1);
    gemm2_tc<<<dim3(DD / 256, TT / 128 + EE - 1), 256, SM_DYN>>>(w2, out, 1);
}

// round 12
// speedup vs baseline: 3.3016x; 1.2400x over previous
#include <cuda_runtime.h>
#include <math.h>
#include <stdint.h>

#define TT 16384
#define DD 1024
#define II 2048
#define EE 16

// tcgen05 only exists in the arch-specific ('a') feature set. The harness also
// compiles a plain compute_103 PTX fallback pass; stub the tcgen05 bodies there
// (that PTX is never executed — the sm_103a cubin is an exact match for the GPU).
#if defined(__CUDA_ARCH__) && !defined(__CUDA_ARCH_FEAT_SM103_ALL)
#define TC_ON 0
#else
#define TC_ON 1
#endif

// ---------------- scratch (device globals; no allocation allowed) ----------------
static __device__ float g_H[(size_t)(TT + 256) * II];   // intermediate, pre-rounded tf32
static __device__ float g_cX[(size_t)TT * DD];          // pre-rounded activations
static __device__ float g_cW1[(size_t)EE * II * DD];
static __device__ float g_cW3[(size_t)EE * II * DD];
static __device__ float g_cW2[(size_t)EE * DD * II];
static __device__ float g_cSG[(size_t)II * DD];
static __device__ float g_cSU[(size_t)II * DD];
static __device__ float g_cSD[(size_t)DD * II];
static __device__ int   g_perm[TT];
static __device__ float g_scale[TT];
static __device__ int   g_eid[TT];
static __device__ int   g_cnt[EE];
static __device__ int   g_off[EE + 1];
static __device__ int   g_cur[EE];

// ---------------- small helpers ----------------
__device__ __forceinline__ unsigned f2tf(float f) {
    unsigned u;
    asm("cvt.rna.tf32.f32 %0, %1;" : "=r"(u) : "f"(f));
    return u;
}
__device__ __forceinline__ float tfr(float f) { return __uint_as_float(f2tf(f)); }

__device__ __forceinline__ uint32_t smem_u32(const void* p) {
    uint32_t a;
    asm("{ .reg .u64 t; cvta.to.shared.u64 t, %1; cvt.u32.u64 %0, t; }" : "=r"(a) : "l"(p));
    return a;
}
__device__ __forceinline__ uint32_t elect1() {
    uint32_t r;
    asm volatile("{ .reg .pred p; elect.sync _|p, 0xFFFFFFFF; selp.b32 %0,1,0,p; }" : "=r"(r));
    return r;
}

#define SWZ128(o) ((o) ^ (((o) >> 3) & 0x70))

__device__ __forceinline__ uint64_t mkdesc(uint32_t addr) {
    // SW128, version=1 (Blackwell), SBO=64, LBO=1, K-major
    return ((uint64_t)2 << 61) | ((uint64_t)1 << 46) | ((uint64_t)64 << 32) |
           ((uint64_t)1 << 16) | ((uint64_t)(addr >> 4) & 0x3FFF);
}

// ---------------- cp.async (baseline sm_80+) ----------------
__device__ __forceinline__ void cpa16(uint32_t dst, const float* src) {
    asm volatile("cp.async.cg.shared.global [%0], [%1], 16;" :: "r"(dst), "l"(src) : "memory");
}
__device__ __forceinline__ void cpa_commit() {
    asm volatile("cp.async.commit_group;" ::: "memory");
}
template <int N> __device__ __forceinline__ void cpa_wait() {
    asm volatile("cp.async.wait_group %0;" :: "n"(N) : "memory");
}

// ---------------- mbarrier ----------------
__device__ __forceinline__ void mbar_init(uint32_t a, uint32_t n) {
    asm volatile("mbarrier.init.shared.b64 [%0], %1;" :: "r"(a), "r"(n) : "memory");
}
__device__ __forceinline__ void mbar_wait(uint32_t a, uint32_t ph) {
    uint32_t done;
    asm volatile(
        "{\n .reg .pred p;\n"
        " mbarrier.try_wait.parity.acquire.cta.shared::cta.b64 p, [%1], %2;\n"
        " selp.b32 %0,1,0,p;\n}"
        : "=r"(done) : "r"(a), "r"(ph) : "memory");
    if (!done) {
        asm volatile(
            "{\n .reg .pred P;\n"
            "WL_%=:\n"
            " mbarrier.try_wait.parity.acquire.cta.shared::cta.b64 P, [%0], %1, 0x989680;\n"
            " @P bra WD_%=;\n"
            " bra WL_%=;\n"
            "WD_%=:\n}"
            :: "r"(a), "r"(ph) : "memory");
    }
}

// ---------------- tcgen05 (guarded: real on sm_103a pass, stub on compute_103) ---
__device__ __forceinline__ void tc_alloc(uint32_t smaddr, uint32_t n) {
#if TC_ON
    asm volatile("tcgen05.alloc.cta_group::1.sync.aligned.shared::cta.b32 [%0], %1;"
                 :: "r"(smaddr), "r"(n) : "memory");
#else
    (void)smaddr; (void)n;
#endif
}
__device__ __forceinline__ void tc_relinq() {
#if TC_ON
    asm volatile("tcgen05.relinquish_alloc_permit.cta_group::1.sync.aligned;");
#endif
}
__device__ __forceinline__ void tc_dealloc(uint32_t t, uint32_t n) {
#if TC_ON
    asm volatile("tcgen05.dealloc.cta_group::1.sync.aligned.b32 %0, %1;" :: "r"(t), "r"(n));
#else
    (void)t; (void)n;
#endif
}
__device__ __forceinline__ void tc_commit(uint32_t mbar) {
#if TC_ON
    asm volatile("tcgen05.commit.cta_group::1.mbarrier::arrive::one.shared::cluster.b64 [%0];"
                 :: "r"(mbar) : "memory");
#else
    (void)mbar;
#endif
}
__device__ __forceinline__ void fence_async() {
    asm volatile("fence.proxy.async.shared::cta;" ::: "memory");
}
__device__ __forceinline__ void tc_fence_after() {
#if TC_ON
    asm volatile("tcgen05.fence::after_thread_sync;" ::: "memory");
#endif
}
__device__ __forceinline__ void tc_wait_ld() {
#if TC_ON
    asm volatile("tcgen05.wait::ld.sync.aligned;" ::: "memory");
#endif
}

__device__ __forceinline__ void mma_tf32(uint32_t d, uint64_t a, uint64_t b,
                                         uint32_t idesc, uint32_t en) {
#if TC_ON
    asm volatile(
        "{\n .reg .pred p;\n"
        " setp.ne.u32 p, %5, 0;\n"
        " tcgen05.mma.cta_group::1.kind::tf32 [%0], %1, %2, %3, {%4,%4,%4,%4}, p;\n}"
        :: "r"(d), "l"(a), "l"(b), "r"(idesc), "r"(0u), "r"(en) : "memory");
#else
    (void)d; (void)a; (void)b; (void)idesc; (void)en;
#endif
}

__device__ __forceinline__ void tc_ld32(uint32_t* r, uint32_t addr) {
#if TC_ON
    asm volatile(
        "tcgen05.ld.sync.aligned.32x32b.x32.b32 "
        "{%0, %1, %2, %3, %4, %5, %6, %7, "
        " %8, %9, %10, %11, %12, %13, %14, %15, "
        " %16, %17, %18, %19, %20, %21, %22, %23, "
        " %24, %25, %26, %27, %28, %29, %30, %31}, [%32];"
        : "=r"(r[0]),  "=r"(r[1]),  "=r"(r[2]),  "=r"(r[3]),
          "=r"(r[4]),  "=r"(r[5]),  "=r"(r[6]),  "=r"(r[7]),
          "=r"(r[8]),  "=r"(r[9]),  "=r"(r[10]), "=r"(r[11]),
          "=r"(r[12]), "=r"(r[13]), "=r"(r[14]), "=r"(r[15]),
          "=r"(r[16]), "=r"(r[17]), "=r"(r[18]), "=r"(r[19]),
          "=r"(r[20]), "=r"(r[21]), "=r"(r[22]), "=r"(r[23]),
          "=r"(r[24]), "=r"(r[25]), "=r"(r[26]), "=r"(r[27]),
          "=r"(r[28]), "=r"(r[29]), "=r"(r[30]), "=r"(r[31])
        : "r"(addr));
#else
#pragma unroll
    for (int i = 0; i < 32; i++) r[i] = 0u;
    (void)addr;
#endif
}

// idesc: dtype=F32(1)@4, atype=TF32(2)@7, btype=TF32(2)@10, N/8@17, M/16@24
#define IDESC_TF32 ((1u << 4) | (2u << 7) | (2u << 10) | ((256u / 8) << 17) | ((128u / 16) << 24))

// smem layout (bytes, 1024-aligned base): A buffers 2x32KB, B buffers 2x32KB, aux
#define SM_A0   0
#define SM_B0   65536
#define SM_AUX  131072
#define SM_DYN  (131072 + 2048)

// stage one K=32 chunk (per-thread 8 A-slots + 8 B-slots of 16B) into buffer b
#define STAGE(b, co) do {                                                  \
    uint32_t ab_ = smb + (uint32_t)(b) * 32768u;                           \
    uint32_t bb_ = smb + 65536u + (uint32_t)(b) * 32768u;                  \
    _Pragma("unroll")                                                      \
    for (int i_ = 0; i_ < 8; i_++) cpa16(ab_ + offA[i_], pA[i_] + (co));   \
    _Pragma("unroll")                                                      \
    for (int i_ = 0; i_ < 8; i_++) cpa16(bb_ + offB[i_], pB[i_] + (co));   \
    cpa_commit();                                                          \
} while (0)

// ---------------- pre-rounding (tf32 RNA, once per launch) ----------------
__global__ void round_copy(const float4* __restrict__ s, float4* __restrict__ d, int n4) {
    int i = blockIdx.x * blockDim.x + threadIdx.x;
    int st = gridDim.x * blockDim.x;
    for (; i < n4; i += st) {
        float4 v = s[i];
        v.x = tfr(v.x); v.y = tfr(v.y); v.z = tfr(v.z); v.w = tfr(v.w);
        d[i] = v;
    }
}

// ---------------- routing ----------------
__global__ void init_counts() {
    int i = threadIdx.x;
    if (i < EE) { g_cnt[i] = 0; g_cur[i] = 0; }
}

__global__ void router_kernel(const float* __restrict__ x, const float* __restrict__ wr) {
    int warp = threadIdx.x >> 5, lane = threadIdx.x & 31;
    int t = blockIdx.x * 8 + warp;
    if (t >= TT) return;
    float acc[EE];
#pragma unroll
    for (int e = 0; e < EE; e++) acc[e] = 0.f;
    const float* xr = x + (size_t)t * DD;
    for (int k = lane; k < DD; k += 32) {
        float xv = xr[k];
#pragma unroll
        for (int e = 0; e < EE; e++) acc[e] += xv * wr[e * DD + k];
    }
#pragma unroll
    for (int e = 0; e < EE; e++) {
#pragma unroll
        for (int o = 16; o > 0; o >>= 1) acc[e] += __shfl_xor_sync(0xffffffffu, acc[e], o);
    }
    if (lane == 0) {
        float best = acc[0]; int bi = 0;
#pragma unroll
        for (int e = 1; e < EE; e++) { if (acc[e] > best) { best = acc[e]; bi = e; } }
        g_eid[t] = bi;
        g_scale[t] = 1.f / (1.f + expf(-best));
        atomicAdd(&g_cnt[bi], 1);
    }
}

__global__ void offsets_kernel() {
    if (threadIdx.x == 0) {
        int s = 0;
        for (int e = 0; e < EE; e++) { g_off[e] = s; s += g_cnt[e]; }
        g_off[EE] = s;
    }
}

__global__ void scatter_kernel() {
    int t = blockIdx.x * blockDim.x + threadIdx.x;
    if (t >= TT) return;
    int e = g_eid[t];
    int p = atomicAdd(&g_cur[e], 1);
    g_perm[g_off[e] + p] = t;
}

// ---------------- GEMM1: H = silu(s*xW1^T)*(s*xW3^T), tile M=256 x N=256 ----------------
// Two M=128 halves share the B tile (gate rows 0..127 = W1, up 128..255 = W3).
__global__ void __launch_bounds__(256) gemm1_tc(
    const float* __restrict__ W1r,
    const float* __restrict__ W3r,
    int routed)
{
    extern __shared__ char smraw[];
    int tid = threadIdx.x, wid = tid >> 5;

    int row0, rows;
    const float *W1p, *W3p;
    if (!routed) {
        row0 = blockIdx.y * 256; rows = 256; W1p = W1r; W3p = W3r;
    } else {
        int base = 0, e = 0, cnte = 0;
        for (e = 0; e < EE; e++) {
            cnte = g_cnt[e];
            int te = (cnte + 255) >> 8;
            if ((int)blockIdx.y < base + te) break;
            base += te;
        }
        if (e >= EE) return;
        int lt = blockIdx.y - base;
        row0 = g_off[e] + lt * 256;
        rows = cnte - lt * 256; if (rows > 256) rows = 256;
        W1p = W1r + (size_t)e * II * DD;
        W3p = W3r + (size_t)e * II * DD;
    }

    uint32_t smr = smem_u32(smraw);
    uint32_t smb = (smr + 1023u) & ~1023u;
    char* sb = smraw + (smb - smr);
    uint32_t aux = smb + SM_AUX;
    float* sS = (float*)(sb + SM_AUX + 64);

    if (wid == 0) { tc_alloc(aux, 512); tc_relinq(); }
    if (tid == 0) { mbar_init(aux + 8, 1); mbar_init(aux + 16, 1); }
    {
        float s = 1.f;
        if (routed) s = (tid < rows) ? g_scale[g_perm[row0 + tid]] : 0.f;
        sS[tid] = s;
    }

    int n0b = blockIdx.x * 128;

    const float* pA[8]; uint32_t offA[8];
#pragma unroll
    for (int i = 0; i < 8; i++) {
        int idx = tid + i * 256, r = idx >> 3, kq = idx & 7;
        int gr;
        if (routed) { int rr = (r < rows) ? r : 0; gr = g_perm[row0 + rr]; }
        else gr = row0 + r;
        pA[i] = g_cX + (size_t)gr * DD + kq * 4;
        offA[i] = SWZ128((uint32_t)(r * 128 + kq * 16));
    }
    const float* pB[8]; uint32_t offB[8];
#pragma unroll
    for (int i = 0; i < 8; i++) {
        int idx = tid + i * 256, r = idx >> 3, kq = idx & 7;
        const float* w = (r < 128) ? (W1p + (size_t)(n0b + r) * DD)
                                   : (W3p + (size_t)(n0b + r - 128) * DD);
        pB[i] = w + kq * 4;
        offB[i] = SWZ128((uint32_t)(r * 128 + kq * 16));
    }
    __syncthreads();

    uint32_t tbase;
    asm volatile("ld.shared.b32 %0, [%1];" : "=r"(tbase) : "r"(aux));

    STAGE(0, 0);

    int ph0 = 0, ph1 = 0;
    const int NC = DD / 32;
    for (int c = 0; c < NC; c++) {
        int b = c & 1;
        if (c + 1 < NC) {
            int nb = b ^ 1;
            if (c >= 1) {
                if (nb) { mbar_wait(aux + 16, ph1); ph1 ^= 1; }
                else    { mbar_wait(aux + 8,  ph0); ph0 ^= 1; }
            }
            STAGE(nb, (c + 1) * 32);
            cpa_wait<1>();
        } else {
            cpa_wait<0>();
        }
        __syncthreads();
        if (wid == 0) {
            fence_async();
            if (elect1()) {
                uint32_t ab = smb + (uint32_t)b * 32768u;
                uint64_t ad0 = mkdesc(ab);
                uint64_t ad1 = mkdesc(ab + 16384u);
                uint64_t bd  = mkdesc(smb + 65536u + (uint32_t)b * 32768u);
#pragma unroll
                for (int ks = 0; ks < 4; ks++) {
                    uint32_t en = (c > 0 || ks > 0) ? 1u : 0u;
                    mma_tf32(tbase,       ad0 + ks * 2, bd + ks * 2, IDESC_TF32, en);
                    mma_tf32(tbase + 256, ad1 + ks * 2, bd + ks * 2, IDESC_TF32, en);
                }
                tc_commit(aux + 8 + b * 8);
            }
        }
    }
    mbar_wait(aux + 16, ph1);   // last chunk (NC-1 odd) committed on buf1
    tc_fence_after();

    {
        int r = tid;
        uint32_t hb = tbase + (uint32_t)(tid >> 7) * 256u;
        bool ok = (!routed) || (r < rows);
        float s = sS[r];
        float* Hrow = g_H + (size_t)(row0 + r) * II + n0b;
#pragma unroll
        for (int p = 0; p < 4; p++) {
            uint32_t gr[32], ur[32];
            tc_ld32(gr, hb + p * 32);
            tc_ld32(ur, hb + 128 + p * 32);
            tc_wait_ld();
            if (ok) {
#pragma unroll
                for (int j = 0; j < 32; j += 4) {
                    float4 h;
                    float gg, uu;
                    gg = __uint_as_float(gr[j + 0]) * s; uu = __uint_as_float(ur[j + 0]) * s;
                    h.x = tfr(gg / (1.f + expf(-gg)) * uu);
                    gg = __uint_as_float(gr[j + 1]) * s; uu = __uint_as_float(ur[j + 1]) * s;
                    h.y = tfr(gg / (1.f + expf(-gg)) * uu);
                    gg = __uint_as_float(gr[j + 2]) * s; uu = __uint_as_float(ur[j + 2]) * s;
                    h.z = tfr(gg / (1.f + expf(-gg)) * uu);
                    gg = __uint_as_float(gr[j + 3]) * s; uu = __uint_as_float(ur[j + 3]) * s;
                    h.w = tfr(gg / (1.f + expf(-gg)) * uu);
                    *(float4*)(Hrow + p * 32 + j) = h;
                }
            }
        }
    }
    __syncthreads();
    if (wid == 0) tc_dealloc(tbase, 512);
}

// ---------------- GEMM2: OUT[:, n0:n0+256] (+)= H @ W2^T, tile M=256 x N=256 ------------
__global__ void __launch_bounds__(256) gemm2_tc(
    const float* __restrict__ Bb,
    float* __restrict__ OUT,
    int routed)
{
    extern __shared__ char smraw[];
    int tid = threadIdx.x, wid = tid >> 5;

    int row0, rows;
    const float* Bp;
    if (!routed) {
        row0 = blockIdx.y * 256; rows = 256; Bp = Bb;
    } else {
        int base = 0, e = 0, cnte = 0;
        for (e = 0; e < EE; e++) {
            cnte = g_cnt[e];
            int te = (cnte + 255) >> 8;
            if ((int)blockIdx.y < base + te) break;
            base += te;
        }
        if (e >= EE) return;
        int lt = blockIdx.y - base;
        row0 = g_off[e] + lt * 256;
        rows = cnte - lt * 256; if (rows > 256) rows = 256;
        Bp = Bb + (size_t)e * DD * II;
    }

    uint32_t smr = smem_u32(smraw);
    uint32_t smb = (smr + 1023u) & ~1023u;
    uint32_t aux = smb + SM_AUX;

    if (wid == 0) { tc_alloc(aux, 512); tc_relinq(); }
    if (tid == 0) { mbar_init(aux + 8, 1); mbar_init(aux + 16, 1); }

    int n0 = blockIdx.x * 256;

    const float* pA[8]; uint32_t offA[8];
#pragma unroll
    for (int i = 0; i < 8; i++) {
        int idx = tid + i * 256, r = idx >> 3, kq = idx & 7;
        pA[i] = g_H + (size_t)(row0 + r) * II + kq * 4;   // padded rows: safe past count
        offA[i] = SWZ128((uint32_t)(r * 128 + kq * 16));
    }
    const float* pB[8]; uint32_t offB[8];
#pragma unroll
    for (int i = 0; i < 8; i++) {
        int idx = tid + i * 256, r = idx >> 3, kq = idx & 7;
        pB[i] = Bp + (size_t)(n0 + r) * II + kq * 4;
        offB[i] = SWZ128((uint32_t)(r * 128 + kq * 16));
    }
    __syncthreads();

    uint32_t tbase;
    asm volatile("ld.shared.b32 %0, [%1];" : "=r"(tbase) : "r"(aux));

    STAGE(0, 0);

    int ph0 = 0, ph1 = 0;
    const int NC = II / 32;
    for (int c = 0; c < NC; c++) {
        int b = c & 1;
        if (c + 1 < NC) {
            int nb = b ^ 1;
            if (c >= 1) {
                if (nb) { mbar_wait(aux + 16, ph1); ph1 ^= 1; }
                else    { mbar_wait(aux + 8,  ph0); ph0 ^= 1; }
            }
            STAGE(nb, (c + 1) * 32);
            cpa_wait<1>();
        } else {
            cpa_wait<0>();
        }
        __syncthreads();
        if (wid == 0) {
            fence_async();
            if (elect1()) {
                uint32_t ab = smb + (uint32_t)b * 32768u;
                uint64_t ad0 = mkdesc(ab);
                uint64_t ad1 = mkdesc(ab + 16384u);
                uint64_t bd  = mkdesc(smb + 65536u + (uint32_t)b * 32768u);
#pragma unroll
                for (int ks = 0; ks < 4; ks++) {
                    uint32_t en = (c > 0 || ks > 0) ? 1u : 0u;
                    mma_tf32(tbase,       ad0 + ks * 2, bd + ks * 2, IDESC_TF32, en);
                    mma_tf32(tbase + 256, ad1 + ks * 2, bd + ks * 2, IDESC_TF32, en);
                }
                tc_commit(aux + 8 + b * 8);
            }
        }
    }
    mbar_wait(aux + 16, ph1);   // NC even -> last chunk on buf1
    tc_fence_after();

    {
        int r = tid;
        uint32_t hb = tbase + (uint32_t)(tid >> 7) * 256u;
        bool ok = (!routed) || (r < rows);
        int tok = 0;
        if (routed && ok) tok = g_perm[row0 + r];
#pragma unroll
        for (int p = 0; p < 8; p++) {
            uint32_t cr[32];
            tc_ld32(cr, hb + p * 32);
            tc_wait_ld();
            if (ok) {
                if (routed) {
                    float* Orow = OUT + (size_t)tok * DD + n0 + p * 32;
#pragma unroll
                    for (int j = 0; j < 32; j += 4) {
                        float4 v = *(float4*)(Orow + j);
                        v.x += __uint_as_float(cr[j + 0]);
                        v.y += __uint_as_float(cr[j + 1]);
                        v.z += __uint_as_float(cr[j + 2]);
                        v.w += __uint_as_float(cr[j + 3]);
                        *(float4*)(Orow + j) = v;
                    }
                } else {
                    float* Orow = OUT + (size_t)(row0 + r) * DD + n0 + p * 32;
#pragma unroll
                    for (int j = 0; j < 32; j += 4) {
                        float4 v;
                        v.x = __uint_as_float(cr[j + 0]);
                        v.y = __uint_as_float(cr[j + 1]);
                        v.z = __uint_as_float(cr[j + 2]);
                        v.w = __uint_as_float(cr[j + 3]);
                        *(float4*)(Orow + j) = v;
                    }
                }
            }
        }
    }
    __syncthreads();
    if (wid == 0) tc_dealloc(tbase, 512);
}

// ---------------- launch ----------------
extern "C" void kernel_launch(void* const* d_in, const int* in_sizes, int n_in,
                              void* d_out, int out_size) {
    (void)in_sizes; (void)n_in; (void)out_size;
    const float* x   = (const float*)d_in[0];
    const float* wr  = (const float*)d_in[1];
    const float* w1  = (const float*)d_in[2];
    const float* w3  = (const float*)d_in[3];
    const float* w2  = (const float*)d_in[4];
    const float* wsg = (const float*)d_in[5];
    const float* wsu = (const float*)d_in[6];
    const float* wsd = (const float*)d_in[7];
    float* out = (float*)d_out;

    static int attr_done = 0;
    if (!attr_done) {
        cudaFuncSetAttribute(gemm1_tc, cudaFuncAttributeMaxDynamicSharedMemorySize, SM_DYN);
        cudaFuncSetAttribute(gemm2_tc, cudaFuncAttributeMaxDynamicSharedMemorySize, SM_DYN);
        attr_done = 1;
    }

    float *cX, *cW1, *cW3, *cW2, *cSG, *cSU, *cSD;
    cudaGetSymbolAddress((void**)&cX,  g_cX);
    cudaGetSymbolAddress((void**)&cW1, g_cW1);
    cudaGetSymbolAddress((void**)&cW3, g_cW3);
    cudaGetSymbolAddress((void**)&cW2, g_cW2);
    cudaGetSymbolAddress((void**)&cSG, g_cSG);
    cudaGetSymbolAddress((void**)&cSU, g_cSU);
    cudaGetSymbolAddress((void**)&cSD, g_cSD);

    const int RB = 1184;  // 148 SMs * 8 blocks
    round_copy<<<RB, 256>>>((const float4*)x,   (float4*)cX,  TT * DD / 4);
    round_copy<<<RB, 256>>>((const float4*)w1,  (float4*)cW1, EE * II * DD / 4);
    round_copy<<<RB, 256>>>((const float4*)w3,  (float4*)cW3, EE * II * DD / 4);
    round_copy<<<RB, 256>>>((const float4*)w2,  (float4*)cW2, EE * DD * II / 4);
    round_copy<<<RB, 256>>>((const float4*)wsg, (float4*)cSG, II * DD / 4);
    round_copy<<<RB, 256>>>((const float4*)wsu, (float4*)cSU, II * DD / 4);
    round_copy<<<RB, 256>>>((const float4*)wsd, (float4*)cSD, DD * II / 4);

    init_counts<<<1, 32>>>();
    router_kernel<<<TT / 8, 256>>>(x, wr);
    offsets_kernel<<<1, 1>>>();
    scatter_kernel<<<TT / 256, 256>>>();

    // shared expert
    gemm1_tc<<<dim3(II / 128, TT / 256), 256, SM_DYN>>>(cSG, cSU, 0);
    gemm2_tc<<<dim3(DD / 256, TT / 256), 256, SM_DYN>>>(cSD, out, 0);

    // routed experts (top-1)
    gemm1_tc<<<dim3(II / 128, TT / 256 + EE - 1), 256, SM_DYN>>>(cW1, cW3, 1);
    gemm2_tc<<<dim3(DD / 256, TT / 256 + EE - 1), 256, SM_DYN>>>(cW2, out, 1);
}